// round 2
// baseline (speedup 1.0000x reference)
#include <cuda_runtime.h>
#include <math.h>

#define B_   32
#define T_   4096
#define C_   1024
#define D_   64
#define TA_  2048   // even tokens
#define TB_  2048   // odd tokens
#define R_   1024   // merged count
#define TUN_ 1024   // unmerged count (TA - R)
#define TOUT_ 3072  // TUN + TB

// ---------------- scratch (static device globals; no runtime alloc) ----------------
__device__ float g_m[(size_t)B_ * T_ * D_];     // normalized metric, 33.5 MB
__device__ float g_nmax[B_ * TA_];
__device__ int   g_nidx[B_ * TA_];
__device__ int   g_unm [B_ * TUN_];
__device__ int   g_off [B_ * (TB_ + 1)];
__device__ int   g_csr [B_ * R_];

#define NEG_INF __int_as_float(0xff800000)

// packed f32x2 helpers (sm_103a): 2 independent rn-FMAs per instruction slot
__device__ __forceinline__ unsigned long long pk2(float lo, float hi) {
    unsigned long long r;
    asm("mov.b64 %0, {%1, %2};" : "=l"(r) : "f"(lo), "f"(hi));
    return r;
}
__device__ __forceinline__ void fma2(unsigned long long& d,
                                     unsigned long long a, unsigned long long b) {
    asm("fma.rn.f32x2 %0, %1, %2, %0;" : "+l"(d) : "l"(a), "l"(b));
}
__device__ __forceinline__ void unpk2(unsigned long long p, float& lo, float& hi) {
    asm("mov.b64 {%0, %1}, %2;" : "=f"(lo), "=f"(hi) : "l"(p));
}

// ---------------- K1: normalize metric rows (one warp per row) ----------------
__global__ __launch_bounds__(256) void k_normalize(const float* __restrict__ metric) {
    int warp = (blockIdx.x * blockDim.x + threadIdx.x) >> 5;
    int lane = threadIdx.x & 31;
    if (warp >= B_ * T_) return;
    const float* row = metric + (size_t)warp * D_;
    float v0 = row[lane];
    float v1 = row[lane + 32];
    float s = v0 * v0 + v1 * v1;
#pragma unroll
    for (int o = 16; o > 0; o >>= 1) s += __shfl_xor_sync(0xffffffffu, s, o);
    float nrm = __fsqrt_rn(s);
    g_m[(size_t)warp * D_ + lane]      = __fdiv_rn(v0, nrm);
    g_m[(size_t)warp * D_ + lane + 32] = __fdiv_rn(v1, nrm);
}

// ---------------- K2: fused GEMM + row max/argmax (packed f32x2 FMAs) ----------------
// Per block: 128 i-rows x (loop over 16 j-tiles of 128). 256 threads, 8x8 per thread.
// Tiles stored k-major (As[k][i], Bs[k][j], pitch 132) so inner loop uses float4 LDS.
__global__ __launch_bounds__(256) void k_argmax() {
    extern __shared__ float sm[];
    float (*As)[132] = (float (*)[132])sm;
    float (*Bs)[132] = (float (*)[132])(sm + 64 * 132);

    const int b  = blockIdx.y;
    const int i0 = blockIdx.x * 128;
    const float* mb = g_m + (size_t)b * T_ * D_;
    const int tid = threadIdx.x;

    // load A tile (even tokens), transpose to k-major
    for (int idx = tid; idx < 128 * 64; idx += 256) {
        int r = idx >> 6, c = idx & 63;
        As[c][r] = mb[(size_t)(2 * (i0 + r)) * D_ + c];
    }

    const int tx = tid & 15, ty = tid >> 4;
    float best[8];
    int   bidx[8];
#pragma unroll
    for (int u = 0; u < 8; u++) { best[u] = NEG_INF; bidx[u] = 0; }

    for (int jt = 0; jt < TB_ / 128; jt++) {
        __syncthreads();
        for (int idx = tid; idx < 128 * 64; idx += 256) {
            int r = idx >> 6, c = idx & 63;
            Bs[c][r] = mb[(size_t)(2 * (jt * 128 + r) + 1) * D_ + c];
        }
        __syncthreads();

        unsigned long long acc[8][4];
#pragma unroll
        for (int u = 0; u < 8; u++)
#pragma unroll
            for (int v = 0; v < 4; v++) acc[u][v] = 0ull;

#pragma unroll 8
        for (int k = 0; k < 64; k++) {
            float4 a0 = *(const float4*)&As[k][4 * ty];
            float4 a1 = *(const float4*)&As[k][64 + 4 * ty];
            float4 b0 = *(const float4*)&Bs[k][4 * tx];
            float4 b1 = *(const float4*)&Bs[k][64 + 4 * tx];
            unsigned long long bp[4] = {pk2(b0.x, b0.y), pk2(b0.z, b0.w),
                                        pk2(b1.x, b1.y), pk2(b1.z, b1.w)};
            float av[8] = {a0.x, a0.y, a0.z, a0.w, a1.x, a1.y, a1.z, a1.w};
#pragma unroll
            for (int u = 0; u < 8; u++) {
                unsigned long long ap = pk2(av[u], av[u]);
#pragma unroll
                for (int v = 0; v < 4; v++) fma2(acc[u][v], ap, bp[v]);
            }
        }

        // running max; iterate j ascending within this thread
        // (strict > keeps the first occurrence, matching jnp.argmax)
#pragma unroll
        for (int v = 0; v < 4; v++) {
            int jb = jt * 128 + ((v < 2) ? (4 * tx + 2 * v) : (64 + 4 * tx + 2 * (v - 2)));
#pragma unroll
            for (int u = 0; u < 8; u++) {
                float lo, hi;
                unpk2(acc[u][v], lo, hi);
                if (lo > best[u]) { best[u] = lo; bidx[u] = jb; }
                if (hi > best[u]) { best[u] = hi; bidx[u] = jb + 1; }
            }
        }
    }

    // reduce across the 16 threads (tx) sharing each i; tie-break: smaller j
#pragma unroll
    for (int u = 0; u < 8; u++) {
        float v = best[u];
        int   id = bidx[u];
#pragma unroll
        for (int o = 8; o > 0; o >>= 1) {
            float ov = __shfl_xor_sync(0xffffffffu, v, o);
            int   oi = __shfl_xor_sync(0xffffffffu, id, o);
            if (ov > v || (ov == v && oi < id)) { v = ov; id = oi; }
        }
        if (tx == 0) {
            int i = i0 + ((u < 4) ? (4 * ty + u) : (64 + 4 * ty + (u - 4)));
            if (i == 0) { v = NEG_INF; id = 0; }  // scores[:,0,:] = -inf
            g_nmax[b * TA_ + i] = v;
            g_nidx[b * TA_ + i] = id;
        }
    }
}

// ---------------- K3: per-batch selection + CSR build (one block per batch) ----------------
__device__ __forceinline__ void bitonic_ull(unsigned long long* a, int n) {
    const int tid = threadIdx.x;
    for (int k = 2; k <= n; k <<= 1) {
        for (int j = k >> 1; j > 0; j >>= 1) {
            __syncthreads();
            for (int i = tid; i < n; i += 1024) {
                int ixj = i ^ j;
                if (ixj > i) {
                    unsigned long long p = a[i], q = a[ixj];
                    bool asc = ((i & k) == 0);
                    if ((p > q) == asc) { a[i] = q; a[ixj] = p; }
                }
            }
        }
    }
    __syncthreads();
}

__global__ __launch_bounds__(1024, 1) void k_select() {
    __shared__ unsigned long long key[2048];
    __shared__ int s_src[1024];
    __shared__ int s_dst[1024];
    const int b = blockIdx.x;
    const int tid = threadIdx.x;

    // key = (~sortable(node_max), idx): ascending sort == (value desc, idx asc)
    // == stable jnp.argsort(-node_max)
    for (int e = tid; e < 2048; e += 1024) {
        unsigned int u = __float_as_uint(g_nmax[b * TA_ + e]);
        u = (u & 0x80000000u) ? ~u : (u | 0x80000000u);
        key[e] = ((unsigned long long)(~u) << 32) | (unsigned int)e;
    }
    bitonic_ull(key, 2048);

    int src_i = (int)(key[tid] & 0xffffffffu);          // rank < r : merged
    int unm_i = (int)(key[1024 + tid] & 0xffffffffu);   // rank >= r: unmerged
    s_src[tid] = src_i;
    s_dst[tid] = g_nidx[b * TA_ + src_i];
    __syncthreads();

    // sort unm indices ascending
    key[tid] = (unsigned long long)(unsigned int)unm_i;
    bitonic_ull(key, 1024);
    g_unm[b * TUN_ + tid] = (int)(key[tid] & 0xffffffffu);
    __syncthreads();

    // sort (dst, rank k) pairs -> CSR grouped by dst, stable in k (deterministic fp order)
    key[tid] = ((unsigned long long)(((unsigned)s_dst[tid] << 10) | (unsigned)tid) << 32)
             | (unsigned int)s_src[tid];
    bitonic_ull(key, 1024);

    int d     = (int)((unsigned)(key[tid] >> 32) >> 10);
    int dprev = (tid == 0) ? -1 : (int)((unsigned)(key[tid - 1] >> 32) >> 10);
    for (int j = dprev + 1; j <= d; j++) g_off[b * (TB_ + 1) + j] = tid;
    if (tid == 1023)
        for (int j = d + 1; j <= TB_; j++) g_off[b * (TB_ + 1) + j] = 1024;
    g_csr[b * R_ + tid] = (int)(key[tid] & 0xffffffffu);
}

// ---------------- K4: gather + merge + divide (one block per output row) ----------------
__global__ __launch_bounds__(256) void k_merge(const float* __restrict__ x,
                                               float* __restrict__ out) {
    int rb = blockIdx.x;
    int b  = rb / TOUT_;
    int r  = rb - b * TOUT_;
    int t  = threadIdx.x;   // 256 threads x float4 = 1024 floats
    const float* xb = x + (size_t)b * T_ * C_;
    float4* orow = (float4*)(out + (size_t)((size_t)b * TOUT_ + r) * C_);

    if (r < TUN_) {
        int src = g_unm[b * TUN_ + r];
        orow[t] = ((const float4*)(xb + (size_t)(2 * src) * C_))[t];
    } else {
        int j = r - TUN_;
        int s = g_off[b * (TB_ + 1) + j];
        int e = g_off[b * (TB_ + 1) + j + 1];
        float4 acc = ((const float4*)(xb + (size_t)(2 * j + 1) * C_))[t];
        for (int p = s; p < e; p++) {
            int src = g_csr[b * R_ + p];
            float4 v = ((const float4*)(xb + (size_t)(2 * src) * C_))[t];
            acc.x += v.x; acc.y += v.y; acc.z += v.z; acc.w += v.w;
        }
        float sz = (float)(1 + e - s);
        acc.x = __fdiv_rn(acc.x, sz);
        acc.y = __fdiv_rn(acc.y, sz);
        acc.z = __fdiv_rn(acc.z, sz);
        acc.w = __fdiv_rn(acc.w, sz);
        orow[t] = acc;
    }
}

// ---------------- launcher ----------------
extern "C" void kernel_launch(void* const* d_in, const int* in_sizes, int n_in,
                              void* d_out, int out_size) {
    const float* x = nullptr;
    const float* metric = nullptr;
    for (int i = 0; i < n_in; i++) {
        long long sz = in_sizes[i];
        if (sz == (long long)B_ * T_ * C_)      x = (const float*)d_in[i];
        else if (sz == (long long)B_ * T_ * D_) metric = (const float*)d_in[i];
    }
    float* out = (float*)d_out;

    k_normalize<<<(B_ * T_) / 8, 256>>>(metric);

    const int smem_bytes = 2 * 64 * 132 * (int)sizeof(float);  // 67.6 KB
    cudaFuncSetAttribute(k_argmax, cudaFuncAttributeMaxDynamicSharedMemorySize, smem_bytes);
    dim3 g2(TA_ / 128, B_);
    k_argmax<<<g2, 256, smem_bytes>>>();

    k_select<<<B_, 1024>>>();

    k_merge<<<B_ * TOUT_, 256>>>(x, out);
}

// round 4
// speedup vs baseline: 1.2698x; 1.2698x over previous
#include <cuda_runtime.h>
#include <cuda_bf16.h>
#include <stdint.h>

#define B_   32
#define T_   4096
#define C_   1024
#define D_   64
#define TA_  2048
#define TB_  2048
#define R_   1024
#define TUN_ 1024
#define TOUT_ 3072

#define NEG_INF __int_as_float(0xff800000)
// |bf16-screened - exact| <= 2^-8 * sum|a_k b_k| + 64*2^-24 <= 0.003918 (unit rows).
// Candidate threshold needs 2x that bound.
#define MARGIN2 0.008f
#define CAND_CAP 1024

// ---------------- scratch (static device globals; no runtime alloc) ----------------
__device__ float g_m[(size_t)B_ * T_ * D_];            // normalized metric fp32
__device__ __nv_bfloat16 g_abf[(size_t)B_ * TA_ * D_]; // bf16(normalized) even rows
__device__ __nv_bfloat16 g_bbf[(size_t)B_ * TB_ * D_]; // bf16(normalized) odd rows
__device__ float g_nmax[B_ * TA_];
__device__ int   g_nidx[B_ * TA_];
__device__ int   g_unm [B_ * TUN_];
__device__ int   g_off [B_ * (TB_ + 1)];
__device__ int   g_csr [B_ * R_];

__device__ __forceinline__ uint32_t smem_u32(const void* p) {
    uint32_t a;
    asm("{ .reg .u64 t; cvta.to.shared.u64 t, %1; cvt.u32.u64 %0, t; }" : "=r"(a) : "l"(p));
    return a;
}
__device__ __forceinline__ uint32_t swz(uint32_t x) { return x ^ (((x >> 7) & 7u) << 4); }

__device__ __forceinline__ void ldsm4(uint32_t& r0, uint32_t& r1, uint32_t& r2, uint32_t& r3,
                                      uint32_t addr) {
    asm volatile("ldmatrix.sync.aligned.m8n8.x4.shared.b16 {%0,%1,%2,%3}, [%4];"
                 : "=r"(r0), "=r"(r1), "=r"(r2), "=r"(r3) : "r"(addr));
}
__device__ __forceinline__ void mma16816(float* d, uint32_t a0, uint32_t a1, uint32_t a2,
                                         uint32_t a3, uint32_t b0, uint32_t b1) {
    asm volatile(
        "mma.sync.aligned.m16n8k16.row.col.f32.bf16.bf16.f32 "
        "{%0,%1,%2,%3}, {%4,%5,%6,%7}, {%8,%9}, {%0,%1,%2,%3};"
        : "+f"(d[0]), "+f"(d[1]), "+f"(d[2]), "+f"(d[3])
        : "r"(a0), "r"(a1), "r"(a2), "r"(a3), "r"(b0), "r"(b1));
}

// ---------------- K1: normalize + fp32 copy + bf16 copies (even/odd split) ----------------
__global__ __launch_bounds__(256) void k_normalize(const float* __restrict__ metric) {
    int row  = (blockIdx.x * blockDim.x + threadIdx.x) >> 5;
    int lane = threadIdx.x & 31;
    if (row >= B_ * T_) return;
    float2 v = *(const float2*)(metric + (size_t)row * D_ + 2 * lane);
    float s = v.x * v.x + v.y * v.y;
#pragma unroll
    for (int o = 16; o > 0; o >>= 1) s += __shfl_xor_sync(0xffffffffu, s, o);
    float nrm = __fsqrt_rn(s);
    float x0 = __fdiv_rn(v.x, nrm);
    float x1 = __fdiv_rn(v.y, nrm);
    *(float2*)(g_m + (size_t)row * D_ + 2 * lane) = make_float2(x0, x1);
    int b = row >> 12;
    int t = row & (T_ - 1);
    __nv_bfloat16* arr = (t & 1) ? g_bbf : g_abf;
    size_t off = ((size_t)b * (T_ / 2) + (t >> 1)) * D_ + 2 * lane;
    *(__nv_bfloat162*)(arr + off) =
        __halves2bfloat162(__float2bfloat16_rn(x0), __float2bfloat16_rn(x1));
}

// ---------------- K2: bf16 HMMA screen (2 passes) + exact fp32 rescore ----------------
// CTA: 128 i-rows (one batch), loops 16 j-tiles of 128. 8 warps, warp = 16 i-rows.
// smem: A-bf16 16K | B0 16K | B1 16K | Afp32 32K | thr 512 | list 4K | val 4K | cnt
#define SM_A    0
#define SM_B0   16384
#define SM_B1   32768
#define SM_AF   49152
#define SM_THR  81920
#define SM_LIST 82432
#define SM_VAL  (82432 + CAND_CAP * 4)
#define SM_CNT  (SM_VAL + CAND_CAP * 4)
#define SM_TOT  (SM_CNT + 16)

__global__ __launch_bounds__(256) void k_screen() {
    extern __shared__ char smem[];
    float* s_afp  = (float*)(smem + SM_AF);
    float* s_thr  = (float*)(smem + SM_THR);
    uint32_t* s_list = (uint32_t*)(smem + SM_LIST);
    float* s_val  = (float*)(smem + SM_VAL);
    int*   s_cnt  = (int*)(smem + SM_CNT);

    const int b   = blockIdx.y;
    const int i0  = blockIdx.x * 128;
    const int tid = threadIdx.x, wid = tid >> 5, lane = tid & 31;
    const uint32_t sb = smem_u32(smem);

    // --- load A bf16 tile (swizzled) and A fp32 tile ---
#pragma unroll
    for (int q = 0; q < 4; q++) {
        int fi = tid + q * 256;           // 1024 x 16B
        int r = fi >> 3, ch = fi & 7;
        uint4 v = *(const uint4*)(g_abf + ((size_t)b * TA_ + i0 + r) * D_ + ch * 8);
        *(uint4*)(smem + SM_A + swz((uint32_t)(r * 128 + ch * 16))) = v;
    }
#pragma unroll
    for (int q = 0; q < 8; q++) {
        int fi = tid + q * 256;           // 2048 x float4
        int r = fi >> 4, c4 = fi & 15;
        float4 v = *(const float4*)(g_m + ((size_t)b * T_ + 2 * (i0 + r)) * D_ + c4 * 4);
        *(float4*)(s_afp + r * 64 + c4 * 4) = v;
    }
    if (tid == 0) *s_cnt = 0;

    // B-tile staging: each thread owns 4x16B of the 16KB tile
    const int lr = tid >> 1, lhalf = tid & 1;
    uint32_t bdst[4];
#pragma unroll
    for (int cc = 0; cc < 4; cc++)
        bdst[cc] = swz((uint32_t)(lr * 128 + (lhalf * 4 + cc) * 16));
    const __nv_bfloat16* gB = g_bbf + (size_t)b * TB_ * D_;

    const int r0l = wid * 16 + (lane >> 2);   // local row for d0/d1
    // lane's mma addressing
    const uint32_t aAddrBase = sb + SM_A;
    const int ar = lane & 15, ac = (lane >> 4) << 3;
    const int bn_l = (lane & 7) + ((lane >> 4) << 3);
    const int bk_l = ((lane >> 3) & 1) << 3;

    float rm0 = NEG_INF, rm1 = NEG_INF;
    float thr0 = 0.f, thr1 = 0.f;

    for (int pass = 0; pass < 2; pass++) {
        // prologue: B(0) -> buf0, B(1) -> regs
        uint4 rb[4];
#pragma unroll
        for (int cc = 0; cc < 4; cc++)
            rb[cc] = *(const uint4*)(gB + (size_t)lr * D_ + (lhalf * 4 + cc) * 8);
#pragma unroll
        for (int cc = 0; cc < 4; cc++) *(uint4*)(smem + SM_B0 + bdst[cc]) = rb[cc];
#pragma unroll
        for (int cc = 0; cc < 4; cc++)
            rb[cc] = *(const uint4*)(gB + (size_t)(128 + lr) * D_ + (lhalf * 4 + cc) * 8);
        __syncthreads();

        for (int jt = 0; jt < 16; jt++) {
            const uint32_t bBase = sb + ((jt & 1) ? SM_B1 : SM_B0);
            float d[16][4];
#pragma unroll
            for (int f = 0; f < 16; f++)
#pragma unroll
                for (int k = 0; k < 4; k++) d[f][k] = 0.0f;

#pragma unroll
            for (int ks = 0; ks < 4; ks++) {
                uint32_t a0, a1, a2, a3;
                ldsm4(a0, a1, a2, a3,
                      aAddrBase + swz((uint32_t)((wid * 16 + ar) * 128 + (ks * 16 + ac) * 2)));
#pragma unroll
                for (int fp = 0; fp < 8; fp++) {
                    uint32_t b0, b1, b2, b3;
                    ldsm4(b0, b1, b2, b3,
                          bBase + swz((uint32_t)((fp * 16 + bn_l) * 128 + (ks * 16 + bk_l) * 2)));
                    mma16816(d[2 * fp],     a0, a1, a2, a3, b0, b1);
                    mma16816(d[2 * fp + 1], a0, a1, a2, a3, b2, b3);
                }
            }

            if (pass == 0) {
#pragma unroll
                for (int f = 0; f < 16; f++) {
                    rm0 = fmaxf(rm0, fmaxf(d[f][0], d[f][1]));
                    rm1 = fmaxf(rm1, fmaxf(d[f][2], d[f][3]));
                }
            } else {
                const int jb0 = jt * 128 + 2 * (lane & 3);
#pragma unroll
                for (int f = 0; f < 16; f++) {
                    int j = jb0 + f * 8;
                    if (d[f][0] >= thr0) { int s = atomicAdd(s_cnt, 1); if (s < CAND_CAP) s_list[s] = ((uint32_t)r0l << 11) | (uint32_t)j; }
                    if (d[f][1] >= thr0) { int s = atomicAdd(s_cnt, 1); if (s < CAND_CAP) s_list[s] = ((uint32_t)r0l << 11) | (uint32_t)(j + 1); }
                    if (d[f][2] >= thr1) { int s = atomicAdd(s_cnt, 1); if (s < CAND_CAP) s_list[s] = ((uint32_t)(r0l + 8) << 11) | (uint32_t)j; }
                    if (d[f][3] >= thr1) { int s = atomicAdd(s_cnt, 1); if (s < CAND_CAP) s_list[s] = ((uint32_t)(r0l + 8) << 11) | (uint32_t)(j + 1); }
                }
            }

            if (jt + 1 < 16) {   // stage B(jt+1) regs -> other buffer
#pragma unroll
                for (int cc = 0; cc < 4; cc++)
                    *(uint4*)(smem + ((jt & 1) ? SM_B0 : SM_B1) + bdst[cc]) = rb[cc];
            }
            __syncthreads();
            if (jt + 2 < 16) {   // prefetch B(jt+2) into regs (overlaps next GEMM)
#pragma unroll
                for (int cc = 0; cc < 4; cc++)
                    rb[cc] = *(const uint4*)(gB + (size_t)((jt + 2) * 128 + lr) * D_ + (lhalf * 4 + cc) * 8);
            }
        }

        if (pass == 0) {   // combine quad lanes -> per-row approx max -> thresholds
#pragma unroll
            for (int o = 1; o < 4; o <<= 1) {
                rm0 = fmaxf(rm0, __shfl_xor_sync(0xffffffffu, rm0, o));
                rm1 = fmaxf(rm1, __shfl_xor_sync(0xffffffffu, rm1, o));
            }
            if ((lane & 3) == 0) {
                s_thr[r0l]     = rm0;
                s_thr[r0l + 8] = rm1;
            }
            __syncthreads();
            thr0 = s_thr[r0l]     - MARGIN2;
            thr1 = s_thr[r0l + 8] - MARGIN2;
        }
    }

    __syncthreads();
    int cnt = *s_cnt; if (cnt > CAND_CAP) cnt = CAND_CAP;

    // exact fp32 rescore: one warp per candidate
    for (int h = wid; h < cnt; h += 8) {
        uint32_t e = s_list[h];
        int r = (int)(e >> 11), j = (int)(e & 2047u);
        const float* brow = g_m + ((size_t)b * T_ + 2 * j + 1) * D_;
        const float* arow = s_afp + r * 64;
        float p = arow[lane] * brow[lane] + arow[lane + 32] * brow[lane + 32];
#pragma unroll
        for (int o = 16; o > 0; o >>= 1) p += __shfl_xor_sync(0xffffffffu, p, o);
        if (lane == 0) s_val[h] = p;
    }
    __syncthreads();

    // per-row exact argmax over candidates (tie-break: smallest j)
    if (tid < 128) {
        int r = tid;
        float best = NEG_INF; int bj = 1 << 30;
        for (int h = 0; h < cnt; h++) {
            uint32_t e = s_list[h];
            if ((int)(e >> 11) == r) {
                float v = s_val[h]; int j = (int)(e & 2047u);
                if (v > best || (v == best && j < bj)) { best = v; bj = j; }
            }
        }
        int gi = i0 + r;
        if (gi == 0) { best = NEG_INF; bj = 0; }   // scores[:,0,:] = -inf
        g_nmax[b * TA_ + gi] = best;
        g_nidx[b * TA_ + gi] = bj;
    }
}

// ---------------- K3: per-batch selection + CSR build ----------------
__device__ __forceinline__ void bitonic_ull(unsigned long long* a, int n) {
    const int tid = threadIdx.x;
    for (int k = 2; k <= n; k <<= 1) {
        for (int j = k >> 1; j > 0; j >>= 1) {
            __syncthreads();
            for (int i = tid; i < n; i += 1024) {
                int ixj = i ^ j;
                if (ixj > i) {
                    unsigned long long p = a[i], q = a[ixj];
                    bool asc = ((i & k) == 0);
                    if ((p > q) == asc) { a[i] = q; a[ixj] = p; }
                }
            }
        }
    }
    __syncthreads();
}

__global__ __launch_bounds__(1024, 1) void k_select() {
    __shared__ unsigned long long key[2048];
    __shared__ int s_src[1024];
    __shared__ int s_dst[1024];
    const int b = blockIdx.x;
    const int tid = threadIdx.x;

    for (int e = tid; e < 2048; e += 1024) {
        unsigned int u = __float_as_uint(g_nmax[b * TA_ + e]);
        u = (u & 0x80000000u) ? ~u : (u | 0x80000000u);
        key[e] = ((unsigned long long)(~u) << 32) | (unsigned int)e;
    }
    bitonic_ull(key, 2048);

    int src_i = (int)(key[tid] & 0xffffffffu);
    int unm_i = (int)(key[1024 + tid] & 0xffffffffu);
    s_src[tid] = src_i;
    s_dst[tid] = g_nidx[b * TA_ + src_i];
    __syncthreads();

    key[tid] = (unsigned long long)(unsigned int)unm_i;
    bitonic_ull(key, 1024);
    g_unm[b * TUN_ + tid] = (int)(key[tid] & 0xffffffffu);
    __syncthreads();

    key[tid] = ((unsigned long long)(((unsigned)s_dst[tid] << 10) | (unsigned)tid) << 32)
             | (unsigned int)s_src[tid];
    bitonic_ull(key, 1024);

    int d     = (int)((unsigned)(key[tid] >> 32) >> 10);
    int dprev = (tid == 0) ? -1 : (int)((unsigned)(key[tid - 1] >> 32) >> 10);
    for (int j = dprev + 1; j <= d; j++) g_off[b * (TB_ + 1) + j] = tid;
    if (tid == 1023)
        for (int j = d + 1; j <= TB_; j++) g_off[b * (TB_ + 1) + j] = 1024;
    g_csr[b * R_ + tid] = (int)(key[tid] & 0xffffffffu);
}

// ---------------- K4: gather + merge + divide ----------------
__global__ __launch_bounds__(256) void k_merge(const float* __restrict__ x,
                                               float* __restrict__ out) {
    int rb = blockIdx.x;
    int b  = rb / TOUT_;
    int r  = rb - b * TOUT_;
    int t  = threadIdx.x;
    const float* xb = x + (size_t)b * T_ * C_;
    float4* orow = (float4*)(out + (size_t)((size_t)b * TOUT_ + r) * C_);

    if (r < TUN_) {
        int src = g_unm[b * TUN_ + r];
        orow[t] = ((const float4*)(xb + (size_t)(2 * src) * C_))[t];
    } else {
        int j = r - TUN_;
        int s = g_off[b * (TB_ + 1) + j];
        int e = g_off[b * (TB_ + 1) + j + 1];
        float4 acc = ((const float4*)(xb + (size_t)(2 * j + 1) * C_))[t];
        for (int p = s; p < e; p++) {
            int src = g_csr[b * R_ + p];
            float4 v = ((const float4*)(xb + (size_t)(2 * src) * C_))[t];
            acc.x += v.x; acc.y += v.y; acc.z += v.z; acc.w += v.w;
        }
        float sz = (float)(1 + e - s);
        acc.x = __fdiv_rn(acc.x, sz);
        acc.y = __fdiv_rn(acc.y, sz);
        acc.z = __fdiv_rn(acc.z, sz);
        acc.w = __fdiv_rn(acc.w, sz);
        orow[t] = acc;
    }
}

// ---------------- launcher ----------------
extern "C" void kernel_launch(void* const* d_in, const int* in_sizes, int n_in,
                              void* d_out, int out_size) {
    const float* x = nullptr;
    const float* metric = nullptr;
    for (int i = 0; i < n_in; i++) {
        long long sz = in_sizes[i];
        if (sz == (long long)B_ * T_ * C_)      x = (const float*)d_in[i];
        else if (sz == (long long)B_ * T_ * D_) metric = (const float*)d_in[i];
    }
    float* out = (float*)d_out;

    k_normalize<<<(B_ * T_) / 8, 256>>>(metric);

    cudaFuncSetAttribute(k_screen, cudaFuncAttributeMaxDynamicSharedMemorySize, SM_TOT);
    dim3 g2(TA_ / 128, B_);
    k_screen<<<g2, 256, SM_TOT>>>();

    k_select<<<B_, 1024>>>();

    k_merge<<<B_ * TOUT_, 256>>>(x, out);
}

// round 5
// speedup vs baseline: 1.6719x; 1.3166x over previous
#include <cuda_runtime.h>
#include <cuda_bf16.h>
#include <stdint.h>

#define B_   32
#define T_   4096
#define C_   1024
#define D_   64
#define TA_  2048
#define TB_  2048
#define R_   1024
#define TUN_ 1024
#define TOUT_ 3072

#define NEG_INF __int_as_float(0xff800000)
// |bf16-screened - exact| <= 2^-8 * sum|a_k b_k| + accum <= 0.004 (unit rows). Need 2x.
#define MARGIN2 0.008f
#define CAND_CAP 4096

// ---------------- scratch (static device globals; no runtime alloc) ----------------
__device__ float g_m[(size_t)B_ * T_ * D_];            // normalized metric fp32
__device__ __nv_bfloat16 g_abf[(size_t)B_ * TA_ * D_]; // bf16(normalized) even rows
__device__ __nv_bfloat16 g_bbf[(size_t)B_ * TB_ * D_]; // bf16(normalized) odd rows
__device__ float g_nmax[B_ * TA_];
__device__ int   g_nidx[B_ * TA_];
__device__ int   g_unm [B_ * TUN_];
__device__ int   g_off [B_ * (TB_ + 1)];
__device__ int   g_csr [B_ * R_];

__device__ __forceinline__ uint32_t smem_u32(const void* p) {
    uint32_t a;
    asm("{ .reg .u64 t; cvta.to.shared.u64 t, %1; cvt.u32.u64 %0, t; }" : "=r"(a) : "l"(p));
    return a;
}
__device__ __forceinline__ uint32_t swz(uint32_t x) { return x ^ (((x >> 7) & 7u) << 4); }

__device__ __forceinline__ void ldsm4(uint32_t& r0, uint32_t& r1, uint32_t& r2, uint32_t& r3,
                                      uint32_t addr) {
    asm volatile("ldmatrix.sync.aligned.m8n8.x4.shared.b16 {%0,%1,%2,%3}, [%4];"
                 : "=r"(r0), "=r"(r1), "=r"(r2), "=r"(r3) : "r"(addr));
}
__device__ __forceinline__ void mma16816(float* d, uint32_t a0, uint32_t a1, uint32_t a2,
                                         uint32_t a3, uint32_t b0, uint32_t b1) {
    asm volatile(
        "mma.sync.aligned.m16n8k16.row.col.f32.bf16.bf16.f32 "
        "{%0,%1,%2,%3}, {%4,%5,%6,%7}, {%8,%9}, {%0,%1,%2,%3};"
        : "+f"(d[0]), "+f"(d[1]), "+f"(d[2]), "+f"(d[3])
        : "r"(a0), "r"(a1), "r"(a2), "r"(a3), "r"(b0), "r"(b1));
}

// ---------------- K1: normalize + fp32 copy + bf16 copies (even/odd split) ----------------
__global__ __launch_bounds__(256) void k_normalize(const float* __restrict__ metric) {
    int row  = (blockIdx.x * blockDim.x + threadIdx.x) >> 5;
    int lane = threadIdx.x & 31;
    if (row >= B_ * T_) return;
    float2 v = *(const float2*)(metric + (size_t)row * D_ + 2 * lane);
    float s = v.x * v.x + v.y * v.y;
#pragma unroll
    for (int o = 16; o > 0; o >>= 1) s += __shfl_xor_sync(0xffffffffu, s, o);
    float nrm = __fsqrt_rn(s);
    float x0 = __fdiv_rn(v.x, nrm);
    float x1 = __fdiv_rn(v.y, nrm);
    *(float2*)(g_m + (size_t)row * D_ + 2 * lane) = make_float2(x0, x1);
    int b = row >> 12;
    int t = row & (T_ - 1);
    __nv_bfloat16* arr = (t & 1) ? g_bbf : g_abf;
    size_t off = ((size_t)b * (T_ / 2) + (t >> 1)) * D_ + 2 * lane;
    *(__nv_bfloat162*)(arr + off) =
        __halves2bfloat162(__float2bfloat16_rn(x0), __float2bfloat16_rn(x1));
}

// ---------------- K2: single-pass bf16 HMMA screen + exact fp32 rescore ----------------
// CTA: 128 i-rows, loops 16 j-tiles of 128. 8 warps, warp = 16 i-rows.
// Collection during pass with running-threshold (superset guarantee), then exact rescore.
#define SM_A    0
#define SM_B0   16384
#define SM_B1   32768
#define SM_LIST 49152
#define SM_BEST (SM_LIST + CAND_CAP * 4)
#define SM_CNT  (SM_BEST + 128 * 8)
#define SM_TOT  (SM_CNT + 16)

__global__ __launch_bounds__(256, 2) void k_screen() {
    extern __shared__ char smem[];
    uint32_t* s_list = (uint32_t*)(smem + SM_LIST);
    unsigned long long* s_best = (unsigned long long*)(smem + SM_BEST);
    int* s_cnt = (int*)(smem + SM_CNT);

    const int b   = blockIdx.y;
    const int i0  = blockIdx.x * 128;
    const int tid = threadIdx.x, wid = tid >> 5, lane = tid & 31;
    const uint32_t sb = smem_u32(smem);

    // --- load A bf16 tile (swizzled) ---
#pragma unroll
    for (int q = 0; q < 4; q++) {
        int fi = tid + q * 256;           // 1024 x 16B
        int r = fi >> 3, ch = fi & 7;
        uint4 v = *(const uint4*)(g_abf + ((size_t)b * TA_ + i0 + r) * D_ + ch * 8);
        *(uint4*)(smem + SM_A + swz((uint32_t)(r * 128 + ch * 16))) = v;
    }
    if (tid == 0) *s_cnt = 0;
    if (tid < 128) s_best[tid] = 0ull;

    // B-tile staging: each thread owns 4x16B of the 16KB tile
    const int lr = tid >> 1, lhalf = tid & 1;
    uint32_t bdst[4];
#pragma unroll
    for (int cc = 0; cc < 4; cc++)
        bdst[cc] = swz((uint32_t)(lr * 128 + (lhalf * 4 + cc) * 16));
    const __nv_bfloat16* gB = g_bbf + (size_t)b * TB_ * D_;

    const int r0l = wid * 16 + (lane >> 2);   // local row for d[.][0..1]; +8 for d[.][2..3]
    const uint32_t aAddrBase = sb + SM_A;
    const int ar = lane & 15, ac = (lane >> 4) << 3;
    const int bn_l = (lane & 7) + ((lane >> 4) << 3);
    const int bk_l = ((lane >> 3) & 1) << 3;

    float run0 = NEG_INF, run1 = NEG_INF;

    // prologue: B(0) -> buf0, B(1) -> regs
    uint4 rb[4];
#pragma unroll
    for (int cc = 0; cc < 4; cc++)
        rb[cc] = *(const uint4*)(gB + (size_t)lr * D_ + (lhalf * 4 + cc) * 8);
#pragma unroll
    for (int cc = 0; cc < 4; cc++) *(uint4*)(smem + SM_B0 + bdst[cc]) = rb[cc];
#pragma unroll
    for (int cc = 0; cc < 4; cc++)
        rb[cc] = *(const uint4*)(gB + (size_t)(128 + lr) * D_ + (lhalf * 4 + cc) * 8);
    __syncthreads();

    for (int jt = 0; jt < 16; jt++) {
        const uint32_t bBase = sb + ((jt & 1) ? SM_B1 : SM_B0);
        float d[16][4];
#pragma unroll
        for (int f = 0; f < 16; f++)
#pragma unroll
            for (int k = 0; k < 4; k++) d[f][k] = 0.0f;

#pragma unroll
        for (int ks = 0; ks < 4; ks++) {
            uint32_t a0, a1, a2, a3;
            ldsm4(a0, a1, a2, a3,
                  aAddrBase + swz((uint32_t)((wid * 16 + ar) * 128 + (ks * 16 + ac) * 2)));
#pragma unroll
            for (int fp = 0; fp < 8; fp++) {
                uint32_t b0, b1, b2, b3;
                ldsm4(b0, b1, b2, b3,
                      bBase + swz((uint32_t)((fp * 16 + bn_l) * 128 + (ks * 16 + bk_l) * 2)));
                mma16816(d[2 * fp],     a0, a1, a2, a3, b0, b1);
                mma16816(d[2 * fp + 1], a0, a1, a2, a3, b2, b3);
            }
        }

        // per-row tile max (quad lanes share rows)
        float tm0 = NEG_INF, tm1 = NEG_INF;
#pragma unroll
        for (int f = 0; f < 16; f++) {
            tm0 = fmaxf(tm0, fmaxf(d[f][0], d[f][1]));
            tm1 = fmaxf(tm1, fmaxf(d[f][2], d[f][3]));
        }
        tm0 = fmaxf(tm0, __shfl_xor_sync(0xffffffffu, tm0, 1));
        tm0 = fmaxf(tm0, __shfl_xor_sync(0xffffffffu, tm0, 2));
        tm1 = fmaxf(tm1, __shfl_xor_sync(0xffffffffu, tm1, 1));
        tm1 = fmaxf(tm1, __shfl_xor_sync(0xffffffffu, tm1, 2));
        const float thr0 = fmaxf(run0, tm0) - MARGIN2;
        const float thr1 = fmaxf(run1, tm1) - MARGIN2;
        run0 = fmaxf(run0, tm0);
        run1 = fmaxf(run1, tm1);

        // collect superset candidates (guaranteed to contain true argmax + exact ties)
        const int jb0 = jt * 128 + 2 * (lane & 3);
#pragma unroll
        for (int f = 0; f < 16; f++) {
            int j = jb0 + f * 8;
            if (d[f][0] >= thr0) { int s = atomicAdd(s_cnt, 1); if (s < CAND_CAP) s_list[s] = ((uint32_t)r0l << 11) | (uint32_t)j; }
            if (d[f][1] >= thr0) { int s = atomicAdd(s_cnt, 1); if (s < CAND_CAP) s_list[s] = ((uint32_t)r0l << 11) | (uint32_t)(j + 1); }
            if (d[f][2] >= thr1) { int s = atomicAdd(s_cnt, 1); if (s < CAND_CAP) s_list[s] = ((uint32_t)(r0l + 8) << 11) | (uint32_t)j; }
            if (d[f][3] >= thr1) { int s = atomicAdd(s_cnt, 1); if (s < CAND_CAP) s_list[s] = ((uint32_t)(r0l + 8) << 11) | (uint32_t)(j + 1); }
        }

        if (jt + 1 < 16) {   // stage B(jt+1) regs -> other buffer
#pragma unroll
            for (int cc = 0; cc < 4; cc++)
                *(uint4*)(smem + ((jt & 1) ? SM_B0 : SM_B1) + bdst[cc]) = rb[cc];
        }
        __syncthreads();
        if (jt + 2 < 16) {   // prefetch B(jt+2) into regs (overlaps next GEMM)
#pragma unroll
            for (int cc = 0; cc < 4; cc++)
                rb[cc] = *(const uint4*)(gB + (size_t)((jt + 2) * 128 + lr) * D_ + (lhalf * 4 + cc) * 8);
        }
    }

    int cnt = *s_cnt; if (cnt > CAND_CAP) cnt = CAND_CAP;

    // exact fp32 rescore: one candidate per thread; packed atomicMax per row
    // key = (sortable(value) << 32) | (2047 - j)  -> max key = (value desc, j asc)
    for (int h = tid; h < cnt; h += 256) {
        uint32_t e = s_list[h];
        int r = (int)(e >> 11), j = (int)(e & 2047u);
        const float4* ar4 = (const float4*)(g_m + ((size_t)b * T_ + 2 * (size_t)(i0 + r)) * D_);
        const float4* br4 = (const float4*)(g_m + ((size_t)b * T_ + 2 * (size_t)j + 1) * D_);
        float acc = 0.0f;
#pragma unroll
        for (int k = 0; k < 16; k++) {
            float4 a4 = ar4[k], b4 = br4[k];
            acc = fmaf(a4.x, b4.x, acc);
            acc = fmaf(a4.y, b4.y, acc);
            acc = fmaf(a4.z, b4.z, acc);
            acc = fmaf(a4.w, b4.w, acc);
        }
        unsigned u = __float_as_uint(acc);
        u = (u & 0x80000000u) ? ~u : (u | 0x80000000u);
        unsigned long long key = ((unsigned long long)u << 32) | (unsigned)(2047 - j);
        atomicMax(&s_best[r], key);
    }
    __syncthreads();

    if (tid < 128) {
        unsigned long long k = s_best[tid];
        unsigned u = (unsigned)(k >> 32);
        float v = __uint_as_float((u & 0x80000000u) ? (u & 0x7fffffffu) : ~u);
        int j = 2047 - (int)(k & 0x7ffu);
        int gi = i0 + tid;
        if (gi == 0) { v = NEG_INF; j = 0; }   // scores[:,0,:] = -inf
        g_nmax[b * TA_ + gi] = v;
        g_nidx[b * TA_ + gi] = j;
    }
}

// ---------------- K3: per-batch selection + CSR build ----------------
__device__ __forceinline__ void bitonic_ull(unsigned long long* a, int n) {
    const int tid = threadIdx.x;
    for (int k = 2; k <= n; k <<= 1) {
        for (int j = k >> 1; j > 0; j >>= 1) {
            __syncthreads();
            for (int i = tid; i < n; i += 1024) {
                int ixj = i ^ j;
                if (ixj > i) {
                    unsigned long long p = a[i], q = a[ixj];
                    bool asc = ((i & k) == 0);
                    if ((p > q) == asc) { a[i] = q; a[ixj] = p; }
                }
            }
        }
    }
    __syncthreads();
}

__global__ __launch_bounds__(1024, 1) void k_select() {
    __shared__ unsigned long long key[2048];
    __shared__ int s_src[1024];
    __shared__ int s_dst[1024];
    const int b = blockIdx.x;
    const int tid = threadIdx.x;

    for (int e = tid; e < 2048; e += 1024) {
        unsigned int u = __float_as_uint(g_nmax[b * TA_ + e]);
        u = (u & 0x80000000u) ? ~u : (u | 0x80000000u);
        key[e] = ((unsigned long long)(~u) << 32) | (unsigned int)e;
    }
    bitonic_ull(key, 2048);

    int src_i = (int)(key[tid] & 0xffffffffu);
    int unm_i = (int)(key[1024 + tid] & 0xffffffffu);
    s_src[tid] = src_i;
    s_dst[tid] = g_nidx[b * TA_ + src_i];
    __syncthreads();

    key[tid] = (unsigned long long)(unsigned int)unm_i;
    bitonic_ull(key, 1024);
    g_unm[b * TUN_ + tid] = (int)(key[tid] & 0xffffffffu);
    __syncthreads();

    key[tid] = ((unsigned long long)(((unsigned)s_dst[tid] << 10) | (unsigned)tid) << 32)
             | (unsigned int)s_src[tid];
    bitonic_ull(key, 1024);

    int d     = (int)((unsigned)(key[tid] >> 32) >> 10);
    int dprev = (tid == 0) ? -1 : (int)((unsigned)(key[tid - 1] >> 32) >> 10);
    for (int j = dprev + 1; j <= d; j++) g_off[b * (TB_ + 1) + j] = tid;
    if (tid == 1023)
        for (int j = d + 1; j <= TB_; j++) g_off[b * (TB_ + 1) + j] = 1024;
    g_csr[b * R_ + tid] = (int)(key[tid] & 0xffffffffu);
}

// ---------------- K4: gather + merge + divide (streaming loads) ----------------
__global__ __launch_bounds__(256) void k_merge(const float* __restrict__ x,
                                               float* __restrict__ out) {
    int rb = blockIdx.x;
    int b  = rb / TOUT_;
    int r  = rb - b * TOUT_;
    int t  = threadIdx.x;
    const float* xb = x + (size_t)b * T_ * C_;
    float4* orow = (float4*)(out + (size_t)((size_t)b * TOUT_ + r) * C_);

    if (r < TUN_) {
        int src = g_unm[b * TUN_ + r];
        orow[t] = __ldcs((const float4*)(xb + (size_t)(2 * src) * C_) + t);
    } else {
        int j = r - TUN_;
        int s = g_off[b * (TB_ + 1) + j];
        int e = g_off[b * (TB_ + 1) + j + 1];
        float4 acc = __ldcs((const float4*)(xb + (size_t)(2 * j + 1) * C_) + t);
        for (int p = s; p < e; p++) {
            int src = g_csr[b * R_ + p];
            float4 v = __ldcs((const float4*)(xb + (size_t)(2 * src) * C_) + t);
            acc.x += v.x; acc.y += v.y; acc.z += v.z; acc.w += v.w;
        }
        float sz = (float)(1 + e - s);
        acc.x = __fdiv_rn(acc.x, sz);
        acc.y = __fdiv_rn(acc.y, sz);
        acc.z = __fdiv_rn(acc.z, sz);
        acc.w = __fdiv_rn(acc.w, sz);
        orow[t] = acc;
    }
}

// ---------------- launcher ----------------
extern "C" void kernel_launch(void* const* d_in, const int* in_sizes, int n_in,
                              void* d_out, int out_size) {
    const float* x = nullptr;
    const float* metric = nullptr;
    for (int i = 0; i < n_in; i++) {
        long long sz = in_sizes[i];
        if (sz == (long long)B_ * T_ * C_)      x = (const float*)d_in[i];
        else if (sz == (long long)B_ * T_ * D_) metric = (const float*)d_in[i];
    }
    float* out = (float*)d_out;

    k_normalize<<<(B_ * T_) / 8, 256>>>(metric);

    cudaFuncSetAttribute(k_screen, cudaFuncAttributeMaxDynamicSharedMemorySize, SM_TOT);
    dim3 g2(TA_ / 128, B_);
    k_screen<<<g2, 256, SM_TOT>>>();

    k_select<<<B_, 1024>>>();

    k_merge<<<B_ * TOUT_, 256>>>(x, out);
}

// round 6
// speedup vs baseline: 1.8730x; 1.1203x over previous
#include <cuda_runtime.h>
#include <cuda_bf16.h>
#include <stdint.h>

#define B_   32
#define T_   4096
#define C_   1024
#define D_   64
#define TA_  2048
#define TB_  2048
#define R_   1024
#define TUN_ 1024
#define TOUT_ 3072

#define NEG_INF __int_as_float(0xff800000)
// |bf16-screened - exact| <= 2^-8 * sum|a_k b_k| + accum <= 0.004 (unit rows). Need 2x.
#define MARGIN2 0.008f
#define CAND_CAP 4096

// ---------------- scratch (static device globals; no runtime alloc) ----------------
__device__ float g_m[(size_t)B_ * T_ * D_];            // normalized metric fp32
__device__ __nv_bfloat16 g_abf[(size_t)B_ * TA_ * D_]; // bf16(normalized) even rows
__device__ __nv_bfloat16 g_bbf[(size_t)B_ * TB_ * D_]; // bf16(normalized) odd rows
__device__ float g_nmax[B_ * TA_];
__device__ int   g_nidx[B_ * TA_];
__device__ int   g_unm [B_ * TUN_];
__device__ int   g_off [B_ * (TB_ + 1)];
__device__ int   g_csr [B_ * R_];

__device__ __forceinline__ uint32_t smem_u32(const void* p) {
    uint32_t a;
    asm("{ .reg .u64 t; cvta.to.shared.u64 t, %1; cvt.u32.u64 %0, t; }" : "=r"(a) : "l"(p));
    return a;
}
__device__ __forceinline__ uint32_t swz(uint32_t x) { return x ^ (((x >> 7) & 7u) << 4); }

__device__ __forceinline__ void cp16(uint32_t dst, const void* src) {
    asm volatile("cp.async.cg.shared.global [%0], [%1], 16;" :: "r"(dst), "l"(src) : "memory");
}
__device__ __forceinline__ void cp_commit() {
    asm volatile("cp.async.commit_group;" ::: "memory");
}
template <int N>
__device__ __forceinline__ void cp_wait() {
    asm volatile("cp.async.wait_group %0;" :: "n"(N) : "memory");
}

__device__ __forceinline__ void ldsm4(uint32_t& r0, uint32_t& r1, uint32_t& r2, uint32_t& r3,
                                      uint32_t addr) {
    asm volatile("ldmatrix.sync.aligned.m8n8.x4.shared.b16 {%0,%1,%2,%3}, [%4];"
                 : "=r"(r0), "=r"(r1), "=r"(r2), "=r"(r3) : "r"(addr));
}
__device__ __forceinline__ void mma16816(float* d, uint32_t a0, uint32_t a1, uint32_t a2,
                                         uint32_t a3, uint32_t b0, uint32_t b1) {
    asm volatile(
        "mma.sync.aligned.m16n8k16.row.col.f32.bf16.bf16.f32 "
        "{%0,%1,%2,%3}, {%4,%5,%6,%7}, {%8,%9}, {%0,%1,%2,%3};"
        : "+f"(d[0]), "+f"(d[1]), "+f"(d[2]), "+f"(d[3])
        : "r"(a0), "r"(a1), "r"(a2), "r"(a3), "r"(b0), "r"(b1));
}

// ---------------- K1: normalize + fp32 copy + bf16 copies (even/odd split) ----------------
__global__ __launch_bounds__(256) void k_normalize(const float* __restrict__ metric) {
    int row  = (blockIdx.x * blockDim.x + threadIdx.x) >> 5;
    int lane = threadIdx.x & 31;
    if (row >= B_ * T_) return;
    float2 v = *(const float2*)(metric + (size_t)row * D_ + 2 * lane);
    float s = v.x * v.x + v.y * v.y;
#pragma unroll
    for (int o = 16; o > 0; o >>= 1) s += __shfl_xor_sync(0xffffffffu, s, o);
    float nrm = __fsqrt_rn(s);
    float x0 = __fdiv_rn(v.x, nrm);
    float x1 = __fdiv_rn(v.y, nrm);
    *(float2*)(g_m + (size_t)row * D_ + 2 * lane) = make_float2(x0, x1);
    int b = row >> 12;
    int t = row & (T_ - 1);
    __nv_bfloat16* arr = (t & 1) ? g_bbf : g_abf;
    size_t off = ((size_t)b * (T_ / 2) + (t >> 1)) * D_ + 2 * lane;
    *(__nv_bfloat162*)(arr + off) =
        __halves2bfloat162(__float2bfloat16_rn(x0), __float2bfloat16_rn(x1));
}

// ---------------- K2: single-pass bf16 HMMA screen + exact fp32 rescore ----------------
#define SM_A    0
#define SM_B0   16384
#define SM_B1   32768
#define SM_LIST 49152
#define SM_BEST (SM_LIST + CAND_CAP * 4)
#define SM_CNT  (SM_BEST + 128 * 8)
#define SM_TOT  (SM_CNT + 16)

__global__ __launch_bounds__(256, 2) void k_screen() {
    extern __shared__ char smem[];
    uint32_t* s_list = (uint32_t*)(smem + SM_LIST);
    unsigned long long* s_best = (unsigned long long*)(smem + SM_BEST);
    int* s_cnt = (int*)(smem + SM_CNT);

    const int b   = blockIdx.y;
    const int i0  = blockIdx.x * 128;
    const int tid = threadIdx.x, wid = tid >> 5, lane = tid & 31;
    const uint32_t sb = smem_u32(smem);

    if (tid == 0) *s_cnt = 0;
    if (tid < 128) s_best[tid] = 0ull;

    // B-tile staging via cp.async: each thread owns 4x16B of the 16KB tile
    const int lr = tid >> 1, lhalf = tid & 1;
    uint32_t bdst[4];
#pragma unroll
    for (int cc = 0; cc < 4; cc++)
        bdst[cc] = swz((uint32_t)(lr * 128 + (lhalf * 4 + cc) * 16));
    const __nv_bfloat16* gB = g_bbf + (size_t)b * TB_ * D_;

    // --- A bf16 tile via cp.async (group0), B(0) (group1), B(1) (group2) ---
#pragma unroll
    for (int q = 0; q < 4; q++) {
        int fi = tid + q * 256;           // 1024 x 16B
        int r = fi >> 3, ch = fi & 7;
        cp16(sb + SM_A + swz((uint32_t)(r * 128 + ch * 16)),
             g_abf + ((size_t)b * TA_ + i0 + r) * D_ + ch * 8);
    }
    cp_commit();
#pragma unroll
    for (int cc = 0; cc < 4; cc++)
        cp16(sb + SM_B0 + bdst[cc], gB + (size_t)lr * D_ + (lhalf * 4 + cc) * 8);
    cp_commit();
#pragma unroll
    for (int cc = 0; cc < 4; cc++)
        cp16(sb + SM_B1 + bdst[cc], gB + (size_t)(128 + lr) * D_ + (lhalf * 4 + cc) * 8);
    cp_commit();

    const int r0l = wid * 16 + (lane >> 2);   // local row for d[.][0..1]; +8 for d[.][2..3]
    const int ar = lane & 15, ac = (lane >> 4) << 3;
    const int bn_l = (lane & 7) + ((lane >> 4) << 3);
    const int bk_l = ((lane >> 3) & 1) << 3;

    // --- hoist A fragments: 4 k-steps x 4 regs, loop-invariant across j-tiles ---
    cp_wait<2>();          // A tile complete
    __syncthreads();
    uint32_t afr[4][4];
#pragma unroll
    for (int ks = 0; ks < 4; ks++)
        ldsm4(afr[ks][0], afr[ks][1], afr[ks][2], afr[ks][3],
              sb + SM_A + swz((uint32_t)((wid * 16 + ar) * 128 + (ks * 16 + ac) * 2)));

    float run0 = NEG_INF, run1 = NEG_INF;

    for (int jt = 0; jt < 16; jt++) {
        if (jt < 15) cp_wait<1>(); else cp_wait<0>();   // B(jt) complete
        __syncthreads();
        const uint32_t bBase = sb + ((jt & 1) ? SM_B1 : SM_B0);

        float d[16][4];
#pragma unroll
        for (int f = 0; f < 16; f++)
#pragma unroll
            for (int k = 0; k < 4; k++) d[f][k] = 0.0f;

#pragma unroll
        for (int ks = 0; ks < 4; ks++) {
#pragma unroll
            for (int fp = 0; fp < 8; fp++) {
                uint32_t b0, b1, b2, b3;
                ldsm4(b0, b1, b2, b3,
                      bBase + swz((uint32_t)((fp * 16 + bn_l) * 128 + (ks * 16 + bk_l) * 2)));
                mma16816(d[2 * fp],     afr[ks][0], afr[ks][1], afr[ks][2], afr[ks][3], b0, b1);
                mma16816(d[2 * fp + 1], afr[ks][0], afr[ks][1], afr[ks][2], afr[ks][3], b2, b3);
            }
        }

        // per-row tile max (quad lanes share rows), pairwise
        float tm0 = NEG_INF, tm1 = NEG_INF;
#pragma unroll
        for (int f = 0; f < 16; f++) {
            tm0 = fmaxf(tm0, fmaxf(d[f][0], d[f][1]));
            tm1 = fmaxf(tm1, fmaxf(d[f][2], d[f][3]));
        }
        tm0 = fmaxf(tm0, __shfl_xor_sync(0xffffffffu, tm0, 1));
        tm0 = fmaxf(tm0, __shfl_xor_sync(0xffffffffu, tm0, 2));
        tm1 = fmaxf(tm1, __shfl_xor_sync(0xffffffffu, tm1, 1));
        tm1 = fmaxf(tm1, __shfl_xor_sync(0xffffffffu, tm1, 2));
        const float thr0 = fmaxf(run0, tm0) - MARGIN2;
        const float thr1 = fmaxf(run1, tm1) - MARGIN2;
        run0 = fmaxf(run0, tm0);
        run1 = fmaxf(run1, tm1);

        // collect superset candidates: pair pre-filter, rare inner path
        const int jb0 = jt * 128 + 2 * (lane & 3);
#pragma unroll
        for (int f = 0; f < 16; f++) {
            int j = jb0 + f * 8;
            if (fmaxf(d[f][0], d[f][1]) >= thr0) {
                if (d[f][0] >= thr0) { int s = atomicAdd(s_cnt, 1); if (s < CAND_CAP) s_list[s] = ((uint32_t)r0l << 11) | (uint32_t)j; }
                if (d[f][1] >= thr0) { int s = atomicAdd(s_cnt, 1); if (s < CAND_CAP) s_list[s] = ((uint32_t)r0l << 11) | (uint32_t)(j + 1); }
            }
            if (fmaxf(d[f][2], d[f][3]) >= thr1) {
                if (d[f][2] >= thr1) { int s = atomicAdd(s_cnt, 1); if (s < CAND_CAP) s_list[s] = ((uint32_t)(r0l + 8) << 11) | (uint32_t)j; }
                if (d[f][3] >= thr1) { int s = atomicAdd(s_cnt, 1); if (s < CAND_CAP) s_list[s] = ((uint32_t)(r0l + 8) << 11) | (uint32_t)(j + 1); }
            }
        }

        __syncthreads();    // all warps done reading buf[jt&1]
        if (jt + 2 < 16) {  // prefetch B(jt+2) into the buffer just freed
#pragma unroll
            for (int cc = 0; cc < 4; cc++)
                cp16(sb + ((jt & 1) ? SM_B1 : SM_B0) + bdst[cc],
                     gB + (size_t)((jt + 2) * 128 + lr) * D_ + (lhalf * 4 + cc) * 8);
            cp_commit();
        } else if (jt < 15) {
            cp_commit();    // keep group accounting aligned
        }
    }

    int cnt = *s_cnt; if (cnt > CAND_CAP) cnt = CAND_CAP;

    // exact fp32 rescore: one candidate per thread; packed atomicMax per row
    // key = (sortable(value) << 32) | (2047 - j)  -> max key = (value desc, j asc)
    for (int h = tid; h < cnt; h += 256) {
        uint32_t e = s_list[h];
        int r = (int)(e >> 11), j = (int)(e & 2047u);
        const float4* ar4 = (const float4*)(g_m + ((size_t)b * T_ + 2 * (size_t)(i0 + r)) * D_);
        const float4* br4 = (const float4*)(g_m + ((size_t)b * T_ + 2 * (size_t)j + 1) * D_);
        float acc = 0.0f;
#pragma unroll
        for (int k = 0; k < 16; k++) {
            float4 a4 = ar4[k], b4 = br4[k];
            acc = fmaf(a4.x, b4.x, acc);
            acc = fmaf(a4.y, b4.y, acc);
            acc = fmaf(a4.z, b4.z, acc);
            acc = fmaf(a4.w, b4.w, acc);
        }
        unsigned u = __float_as_uint(acc);
        u = (u & 0x80000000u) ? ~u : (u | 0x80000000u);
        unsigned long long key = ((unsigned long long)u << 32) | (unsigned)(2047 - j);
        atomicMax(&s_best[r], key);
    }
    __syncthreads();

    if (tid < 128) {
        unsigned long long k = s_best[tid];
        unsigned u = (unsigned)(k >> 32);
        float v = __uint_as_float((u & 0x80000000u) ? (u & 0x7fffffffu) : ~u);
        int j = 2047 - (int)(k & 0x7ffu);
        int gi = i0 + tid;
        if (gi == 0) { v = NEG_INF; j = 0; }   // scores[:,0,:] = -inf
        g_nmax[b * TA_ + gi] = v;
        g_nidx[b * TA_ + gi] = j;
    }
}

// ---------------- K3: per-batch selection + CSR build ----------------
__device__ __forceinline__ void bitonic_ull(unsigned long long* a, int n) {
    const int tid = threadIdx.x;
    for (int k = 2; k <= n; k <<= 1) {
        for (int j = k >> 1; j > 0; j >>= 1) {
            __syncthreads();
            for (int i = tid; i < n; i += 1024) {
                int ixj = i ^ j;
                if (ixj > i) {
                    unsigned long long p = a[i], q = a[ixj];
                    bool asc = ((i & k) == 0);
                    if ((p > q) == asc) { a[i] = q; a[ixj] = p; }
                }
            }
        }
    }
    __syncthreads();
}

__global__ __launch_bounds__(1024, 1) void k_select() {
    __shared__ unsigned long long key[2048];
    __shared__ int s_src[1024];
    __shared__ int s_dst[1024];
    const int b = blockIdx.x;
    const int tid = threadIdx.x;

    for (int e = tid; e < 2048; e += 1024) {
        unsigned int u = __float_as_uint(g_nmax[b * TA_ + e]);
        u = (u & 0x80000000u) ? ~u : (u | 0x80000000u);
        key[e] = ((unsigned long long)(~u) << 32) | (unsigned int)e;
    }
    bitonic_ull(key, 2048);

    int src_i = (int)(key[tid] & 0xffffffffu);
    int unm_i = (int)(key[1024 + tid] & 0xffffffffu);
    s_src[tid] = src_i;
    s_dst[tid] = g_nidx[b * TA_ + src_i];
    __syncthreads();

    key[tid] = (unsigned long long)(unsigned int)unm_i;
    bitonic_ull(key, 1024);
    g_unm[b * TUN_ + tid] = (int)(key[tid] & 0xffffffffu);
    __syncthreads();

    key[tid] = ((unsigned long long)(((unsigned)s_dst[tid] << 10) | (unsigned)tid) << 32)
             | (unsigned int)s_src[tid];
    bitonic_ull(key, 1024);

    int d     = (int)((unsigned)(key[tid] >> 32) >> 10);
    int dprev = (tid == 0) ? -1 : (int)((unsigned)(key[tid - 1] >> 32) >> 10);
    for (int j = dprev + 1; j <= d; j++) g_off[b * (TB_ + 1) + j] = tid;
    if (tid == 1023)
        for (int j = d + 1; j <= TB_; j++) g_off[b * (TB_ + 1) + j] = 1024;
    g_csr[b * R_ + tid] = (int)(key[tid] & 0xffffffffu);
}

// ---------------- K4: gather + merge + divide (warp-per-row, MLP 8) ----------------
__global__ __launch_bounds__(256) void k_merge(const float* __restrict__ x,
                                               float* __restrict__ out) {
    int wg   = blockIdx.x * 8 + (threadIdx.x >> 5);
    int b    = wg / TOUT_;
    int r    = wg - b * TOUT_;
    int lane = threadIdx.x & 31;
    const float* xb = x + (size_t)b * T_ * C_;
    float4* orow = (float4*)(out + (size_t)((size_t)b * TOUT_ + r) * C_);

    if (r < TUN_) {
        int src = g_unm[b * TUN_ + r];
        const float4* s4 = (const float4*)(xb + (size_t)(2 * src) * C_);
        float4 v[8];
#pragma unroll
        for (int c = 0; c < 8; c++) v[c] = __ldcs(s4 + lane + 32 * c);
#pragma unroll
        for (int c = 0; c < 8; c++) orow[lane + 32 * c] = v[c];
    } else {
        int j = r - TUN_;
        int s = g_off[b * (TB_ + 1) + j];
        int e = g_off[b * (TB_ + 1) + j + 1];
        const float4* d4 = (const float4*)(xb + (size_t)(2 * j + 1) * C_);
        float4 acc[8];
#pragma unroll
        for (int c = 0; c < 8; c++) acc[c] = __ldcs(d4 + lane + 32 * c);
        for (int p = s; p < e; p++) {
            int src = g_csr[b * R_ + p];
            const float4* s4 = (const float4*)(xb + (size_t)(2 * src) * C_);
#pragma unroll
            for (int c = 0; c < 8; c++) {
                float4 v = __ldcs(s4 + lane + 32 * c);
                acc[c].x += v.x; acc[c].y += v.y; acc[c].z += v.z; acc[c].w += v.w;
            }
        }
        float sz = (float)(1 + e - s);
#pragma unroll
        for (int c = 0; c < 8; c++) {
            acc[c].x = __fdiv_rn(acc[c].x, sz);
            acc[c].y = __fdiv_rn(acc[c].y, sz);
            acc[c].z = __fdiv_rn(acc[c].z, sz);
            acc[c].w = __fdiv_rn(acc[c].w, sz);
            orow[lane + 32 * c] = acc[c];
        }
    }
}

// ---------------- launcher ----------------
extern "C" void kernel_launch(void* const* d_in, const int* in_sizes, int n_in,
                              void* d_out, int out_size) {
    const float* x = nullptr;
    const float* metric = nullptr;
    for (int i = 0; i < n_in; i++) {
        long long sz = in_sizes[i];
        if (sz == (long long)B_ * T_ * C_)      x = (const float*)d_in[i];
        else if (sz == (long long)B_ * T_ * D_) metric = (const float*)d_in[i];
    }
    float* out = (float*)d_out;

    k_normalize<<<(B_ * T_) / 8, 256>>>(metric);

    cudaFuncSetAttribute(k_screen, cudaFuncAttributeMaxDynamicSharedMemorySize, SM_TOT);
    dim3 g2(TA_ / 128, B_);
    k_screen<<<g2, 256, SM_TOT>>>();

    k_select<<<B_, 1024>>>();

    k_merge<<<B_ * TOUT_ / 8, 256>>>(x, out);
}